// round 1
// baseline (speedup 1.0000x reference)
#include <cuda_runtime.h>
#include <math.h>

#define NN     8000
#define NE     64000
#define BATCH  64
#define NG     12
#define HID    128
#define BAS    128
#define LAY    3
#define IN_S   16
#define OUT_S  8
#define WIDE   4
#define WHID   (WIDE*HID)   // 512

// ---------------- device scratch (static, no allocs) ----------------
__device__ float g_grid0[NG*3];
__device__ float g_kbsh[NG*NG*BAS];
__device__ float g_fk[LAY*NG*NG*HID];
__device__ float g_nodegrid[NN*NG*3];
__device__ float g_h[NN*NG*HID];
__device__ float g_agg[NN*NG*HID];
__device__ float g_readout[NN*NG*9];
__device__ float g_kbsp[(size_t)NE*NG*BAS];   // 393 MB

__device__ __forceinline__ float gelu(float x) {
    return x * 0.5f * (1.0f + erff(x * 0.70710678118654752f));
}

// ---------------- K0: fibonacci sphere ----------------
__global__ void k_init_grid0() {
    int i = threadIdx.x;
    if (i < NG) {
        const float golden = 1.6180339887498949f;
        const float twopi  = 6.2831853071795865f;
        float fi = (float)i;
        float theta = (twopi * fi) / golden;
        float z = 1.0f - (2.0f * fi + 1.0f) / (float)NG;
        float r = sqrtf(fmaxf(1.0f - z * z, 0.0f));
        g_grid0[i*3+0] = r * cosf(theta);
        g_grid0[i*3+1] = r * sinf(theta);
        g_grid0[i*3+2] = z;
    }
}

// ---------------- K1: kb_sh (144 rows) ----------------
__global__ void k_kbsh(const float* __restrict__ Wsh1, const float* __restrict__ bsh1,
                       const float* __restrict__ Wsh2, const float* __restrict__ bsh2) {
    int row = blockIdx.x;            // p*12+o
    int p = row / NG, o = row % NG;
    int c = threadIdx.x;             // 128 threads
    __shared__ float h1[HID];
    float t = g_grid0[p*3+0]*g_grid0[o*3+0] + g_grid0[p*3+1]*g_grid0[o*3+1]
            + g_grid0[p*3+2]*g_grid0[o*3+2];
    float pf0 = t, pf1 = t*t, pf2 = t*t*t;
    float a = bsh1[c] + pf0*Wsh1[0*HID+c] + pf1*Wsh1[1*HID+c] + pf2*Wsh1[2*HID+c];
    h1[c] = gelu(a);
    __syncthreads();
    float acc = bsh2[c];
    #pragma unroll 8
    for (int k = 0; k < HID; k++) acc += h1[k] * Wsh2[k*HID+c];
    g_kbsh[row*BAS + c] = gelu(acc);
}

// ---------------- K2: fk[l,p,o,:] = kb_sh[p,o,:] @ Wfk[l] ----------------
__global__ void k_fk(const float* __restrict__ Wfk) {
    int blk = blockIdx.x;            // l*144 + row
    int l = blk / (NG*NG), row = blk % (NG*NG);
    int c = threadIdx.x;
    __shared__ float kb[BAS];
    kb[c] = g_kbsh[row*BAS + c];
    __syncthreads();
    const float* W = Wfk + (size_t)l*BAS*HID;
    float acc = 0.f;
    #pragma unroll 8
    for (int b = 0; b < BAS; b++) acc += kb[b] * W[b*HID + c];
    g_fk[((size_t)l*NG*NG + row)*HID + c] = acc;
}

// ---------------- K3: node_grid + h0 + zero readout ----------------
__global__ void k_nodeinit(const float* __restrict__ x, const float* __restrict__ vec,
                           const float* __restrict__ Q, const int* __restrict__ batch,
                           const float* __restrict__ Wemb) {
    int i = blockIdx.x;
    int t = threadIdx.x;
    __shared__ float ng[NG][3];
    __shared__ float xv[NG][2];
    __shared__ float xs[IN_S];
    int b = batch[i];
    if (t < 36) {
        int n = t / 3, d = t % 3;
        float s = 0.f;
        #pragma unroll
        for (int j = 0; j < 3; j++) s += Q[b*9 + d*3 + j] * g_grid0[n*3 + j];
        ng[n][d] = s;
        g_nodegrid[i*36 + t] = s;
    }
    if (t >= 64 && t < 64 + IN_S) xs[t-64] = x[i*IN_S + (t-64)];
    if (t < 108) g_readout[i*108 + t] = 0.f;
    __syncthreads();
    if (t < 24) {
        int n = t / 2, v = t % 2;
        xv[n][v] = vec[i*6 + v*3 + 0]*ng[n][0] + vec[i*6 + v*3 + 1]*ng[n][1]
                 + vec[i*6 + v*3 + 2]*ng[n][2];
    }
    __syncthreads();
    int c = t;
    float hx = 0.f;
    #pragma unroll
    for (int s = 0; s < IN_S; s++) hx += xs[s] * Wemb[s*HID + c];
    float w16 = Wemb[16*HID + c], w17 = Wemb[17*HID + c];
    #pragma unroll
    for (int n = 0; n < NG; n++)
        g_h[(size_t)i*NG*HID + n*HID + c] = hx + xv[n][0]*w16 + xv[n][1]*w17;
}

// ---------------- K4: kb_sp per edge ----------------
__global__ void k_kbsp(const float* __restrict__ pos, const int* __restrict__ ei,
                       const float* __restrict__ Wsp1, const float* __restrict__ bsp1,
                       const float* __restrict__ Wsp2, const float* __restrict__ bsp2) {
    int e = blockIdx.x;
    int c = threadIdx.x;
    __shared__ float pf[NG][16];      // 14 used
    __shared__ float h1[NG][HID];
    int s = ei[e], r = ei[NE + e];
    float rx = pos[s*3+0] - pos[r*3+0];
    float ry = pos[s*3+1] - pos[r*3+1];
    float rz = pos[s*3+2] - pos[r*3+2];
    if (c < NG) {
        int n = c;
        float gx = g_nodegrid[r*36 + n*3 + 0];
        float gy = g_nodegrid[r*36 + n*3 + 1];
        float gz = g_nodegrid[r*36 + n*3 + 2];
        float a = rx*gx + ry*gy + rz*gz;                // inv1
        float vx = rx - a*gx, vy = ry - a*gy, vz = rz - a*gz;
        float bb = sqrtf(vx*vx + vy*vy + vz*vz);        // inv2
        pf[n][0] = a;   pf[n][1] = bb;
        pf[n][2] = a*a; pf[n][3] = a*bb; pf[n][4] = bb*a; pf[n][5] = bb*bb;
        pf[n][6]  = a*a*a;   pf[n][7]  = a*a*bb;
        pf[n][8]  = a*bb*a;  pf[n][9]  = a*bb*bb;
        pf[n][10] = bb*a*a;  pf[n][11] = bb*a*bb;
        pf[n][12] = bb*bb*a; pf[n][13] = bb*bb*bb;
    }
    __syncthreads();
    float bs1 = bsp1[c];
    #pragma unroll
    for (int n = 0; n < NG; n++) {
        float a = bs1;
        #pragma unroll
        for (int j = 0; j < 14; j++) a += pf[n][j] * Wsp1[j*HID + c];
        h1[n][c] = gelu(a);
    }
    __syncthreads();
    float acc[NG];
    #pragma unroll
    for (int n = 0; n < NG; n++) acc[n] = 0.f;
    for (int k = 0; k < HID; k += 4) {
        float w0 = Wsp2[(k+0)*HID + c];
        float w1 = Wsp2[(k+1)*HID + c];
        float w2 = Wsp2[(k+2)*HID + c];
        float w3 = Wsp2[(k+3)*HID + c];
        #pragma unroll
        for (int n = 0; n < NG; n++) {
            float4 hv = *(const float4*)&h1[n][k];
            acc[n] += hv.x*w0 + hv.y*w1 + hv.z*w2 + hv.w*w3;
        }
    }
    float bs2 = bsp2[c];
    float* out = g_kbsp + (size_t)e*NG*BAS;
    #pragma unroll
    for (int n = 0; n < NG; n++) out[n*HID + c] = gelu(acc[n] + bs2);
}

// ---------------- zero helper ----------------
__global__ void k_zero_agg() {
    size_t idx = (size_t)blockIdx.x * blockDim.x + threadIdx.x;
    size_t tot = (size_t)NN*NG*HID;
    if (idx < tot) g_agg[idx] = 0.f;
}

// ---------------- K6: edge message + scatter (per layer) ----------------
__global__ void k_edge(const float* __restrict__ Wk, const int* __restrict__ ei, int l) {
    int e = blockIdx.x;
    int c = threadIdx.x;
    __shared__ float kb[NG][HID];
    {
        const float4* src = (const float4*)(g_kbsp + (size_t)e*NG*BAS);
        float4* dst = (float4*)&kb[0][0];
        for (int i = c; i < NG*HID/4; i += HID) dst[i] = src[i];
    }
    __syncthreads();
    int s = ei[e], r = ei[NE + e];
    const float* W = Wk + (size_t)l*BAS*HID;
    float acc[NG];
    #pragma unroll
    for (int n = 0; n < NG; n++) acc[n] = 0.f;
    for (int b = 0; b < BAS; b += 4) {
        float w0 = W[(b+0)*HID + c];
        float w1 = W[(b+1)*HID + c];
        float w2 = W[(b+2)*HID + c];
        float w3 = W[(b+3)*HID + c];
        #pragma unroll
        for (int n = 0; n < NG; n++) {
            float4 kv = *(const float4*)&kb[n][b];
            acc[n] += kv.x*w0 + kv.y*w1 + kv.z*w2 + kv.w*w3;
        }
    }
    const float* hs = g_h + (size_t)s*NG*HID;
    float* ag = g_agg + (size_t)r*NG*HID;
    #pragma unroll
    for (int n = 0; n < NG; n++) {
        float m = hs[n*HID + c] * acc[n];
        atomicAdd(&ag[n*HID + c], m);
    }
}

// ---------------- K7: conv + LN + MLP + residual + readout (per layer) ----
__global__ void k_node(const float* __restrict__ bconv,
                       const float* __restrict__ lng, const float* __restrict__ lnb,
                       const float* __restrict__ W1, const float* __restrict__ b1,
                       const float* __restrict__ W2, const float* __restrict__ b2,
                       const float* __restrict__ Wro, const float* __restrict__ bro,
                       int l) {
    int i = blockIdx.x;
    int c = threadIdx.x;   // 128
    __shared__ float sA[NG][HID];    // agg
    __shared__ float sH[NG][HID];    // x2 -> hn -> h_new
    __shared__ float sU[NG][WHID];   // mlp hidden (24 KB)
    __shared__ float mu[NG], rstd[NG];
    {
        const float4* src = (const float4*)(g_agg + (size_t)i*NG*HID);
        float4* dst = (float4*)&sA[0][0];
        for (int k = c; k < NG*HID/4; k += HID) dst[k] = src[k];
    }
    __syncthreads();
    // conv: x2[p][c] = sum_o sA[o][c]*fk[l,p,o,c]/12 + bconv
    const float* fkl = g_fk + (size_t)l*NG*NG*HID;
    float bcv = bconv[l*HID + c];
    #pragma unroll
    for (int p = 0; p < NG; p++) {
        float s = 0.f;
        #pragma unroll
        for (int o = 0; o < NG; o++) s += sA[o][c] * fkl[(p*NG + o)*HID + c];
        sH[p][c] = s * (1.0f/NG) + bcv;
    }
    __syncthreads();
    // LN stats: threads 0..11
    if (c < NG) {
        float s = 0.f, s2 = 0.f;
        for (int k = 0; k < HID; k++) { float v = sH[c][k]; s += v; s2 += v*v; }
        float m = s / HID;
        float var = s2 / HID - m*m;
        mu[c] = m; rstd[c] = rsqrtf(var + 1e-5f);
    }
    __syncthreads();
    float g = lng[l*HID + c], bb = lnb[l*HID + c];
    float hn[NG];
    #pragma unroll
    for (int p = 0; p < NG; p++) hn[p] = (sH[p][c] - mu[p]) * rstd[p] * g + bb;
    __syncthreads();
    #pragma unroll
    for (int p = 0; p < NG; p++) sH[p][c] = hn[p];
    __syncthreads();
    // MLP layer 1: 128 -> 512
    const float* W1l = W1 + (size_t)l*HID*WHID;
    for (int jj = 0; jj < 4; jj++) {
        int j = c + jj*HID;
        float acc[NG];
        #pragma unroll
        for (int p = 0; p < NG; p++) acc[p] = 0.f;
        for (int k = 0; k < HID; k += 4) {
            float w0 = W1l[(k+0)*WHID + j];
            float w1 = W1l[(k+1)*WHID + j];
            float w2 = W1l[(k+2)*WHID + j];
            float w3 = W1l[(k+3)*WHID + j];
            #pragma unroll
            for (int p = 0; p < NG; p++) {
                float4 hv = *(const float4*)&sH[p][k];
                acc[p] += hv.x*w0 + hv.y*w1 + hv.z*w2 + hv.w*w3;
            }
        }
        float bj = b1[l*WHID + j];
        #pragma unroll
        for (int p = 0; p < NG; p++) sU[p][j] = gelu(acc[p] + bj);
    }
    __syncthreads();
    // MLP layer 2: 512 -> 128, residual, store h
    const float* W2l = W2 + (size_t)l*WHID*HID;
    float acc[NG];
    #pragma unroll
    for (int p = 0; p < NG; p++) acc[p] = 0.f;
    for (int j = 0; j < WHID; j += 4) {
        float w0 = W2l[(j+0)*HID + c];
        float w1 = W2l[(j+1)*HID + c];
        float w2 = W2l[(j+2)*HID + c];
        float w3 = W2l[(j+3)*HID + c];
        #pragma unroll
        for (int p = 0; p < NG; p++) {
            float4 uv = *(const float4*)&sU[p][j];
            acc[p] += uv.x*w0 + uv.y*w1 + uv.z*w2 + uv.w*w3;
        }
    }
    float b2c = b2[l*HID + c];
    float* hrow = g_h + (size_t)i*NG*HID;
    __syncthreads();
    #pragma unroll
    for (int p = 0; p < NG; p++) {
        float hnew = hrow[p*HID + c] + acc[p] + b2c;
        hrow[p*HID + c] = hnew;
        sH[p][c] = hnew;
    }
    __syncthreads();
    // readout accumulation: threads 0..107 -> (p,m)
    if (c < NG*9) {
        int p = c / 9, m = c % 9;
        const float* Wrol = Wro + (size_t)l*HID*9;
        float s = 0.f;
        for (int k = 0; k < HID; k++) s += sH[p][k] * Wrol[k*9 + m];
        g_readout[(size_t)i*108 + p*9 + m] += (s + bro[l*9 + m]) * (1.0f/LAY);
    }
}

// ---------------- K8: final reduction ----------------
__global__ void k_zero_out(float* out, int n) {
    int t = threadIdx.x;
    if (t < n) out[t] = 0.f;
}

__global__ void k_final(const int* __restrict__ batch, float* __restrict__ out) {
    int i = blockIdx.x;
    int t = threadIdx.x;
    int b = batch[i];
    if (t < OUT_S) {
        float s = 0.f;
        #pragma unroll
        for (int n = 0; n < NG; n++) s += g_readout[(size_t)i*108 + n*9 + t];
        atomicAdd(&out[b*OUT_S + t], s * (1.0f/NG));
    } else if (t < OUT_S + 3) {
        int d = t - OUT_S;
        float s = 0.f;
        #pragma unroll
        for (int n = 0; n < NG; n++)
            s += g_readout[(size_t)i*108 + n*9 + 8] * g_nodegrid[i*36 + n*3 + d];
        atomicAdd(&out[BATCH*OUT_S + b*3 + d], s * (1.0f/NG));
    }
}

// ---------------- launch ----------------
extern "C" void kernel_launch(void* const* d_in, const int* in_sizes, int n_in,
                              void* d_out, int out_size) {
    const float* x     = (const float*)d_in[0];
    const float* vec   = (const float*)d_in[1];
    const float* pos   = (const float*)d_in[2];
    const float* Q     = (const float*)d_in[3];
    const float* Wsp1  = (const float*)d_in[4];
    const float* bsp1  = (const float*)d_in[5];
    const float* Wsp2  = (const float*)d_in[6];
    const float* bsp2  = (const float*)d_in[7];
    const float* Wsh1  = (const float*)d_in[8];
    const float* bsh1  = (const float*)d_in[9];
    const float* Wsh2  = (const float*)d_in[10];
    const float* bsh2  = (const float*)d_in[11];
    const float* Wemb  = (const float*)d_in[12];
    const float* Wk    = (const float*)d_in[13];
    const float* Wfk   = (const float*)d_in[14];
    const float* bconv = (const float*)d_in[15];
    const float* lng   = (const float*)d_in[16];
    const float* lnb   = (const float*)d_in[17];
    const float* W1    = (const float*)d_in[18];
    const float* b1    = (const float*)d_in[19];
    const float* W2    = (const float*)d_in[20];
    const float* b2    = (const float*)d_in[21];
    const float* Wro   = (const float*)d_in[22];
    const float* bro   = (const float*)d_in[23];
    const int*   ei    = (const int*)d_in[24];
    const int*   batch = (const int*)d_in[25];
    float* out = (float*)d_out;

    k_init_grid0<<<1, 32>>>();
    k_kbsh<<<NG*NG, HID>>>(Wsh1, bsh1, Wsh2, bsh2);
    k_fk<<<LAY*NG*NG, HID>>>(Wfk);
    k_nodeinit<<<NN, HID>>>(x, vec, Q, batch, Wemb);
    k_kbsp<<<NE, HID>>>(pos, ei, Wsp1, bsp1, Wsp2, bsp2);

    for (int l = 0; l < LAY; l++) {
        int tot = NN*NG*HID;
        k_zero_agg<<<(tot + 255)/256, 256>>>();
        k_edge<<<NE, HID>>>(Wk, ei, l);
        k_node<<<NN, HID>>>(bconv, lng, lnb, W1, b1, W2, b2, Wro, bro, l);
    }

    k_zero_out<<<1, 1024>>>(out, out_size);
    k_final<<<NN, 32>>>(batch, out);
}

// round 2
// speedup vs baseline: 1.0012x; 1.0012x over previous
#include <cuda_runtime.h>
#include <math.h>

#define NN     8000
#define NE     64000
#define BATCH  64
#define NG     12
#define HID    128
#define BAS    128
#define LAY    3
#define IN_S   16
#define OUT_S  8
#define WIDE   4
#define WHID   (WIDE*HID)   // 512

// ---------------- device scratch (static, no allocs) ----------------
__device__ float g_grid0[NG*3];
__device__ float g_kbsh[NG*NG*BAS];
__device__ float g_fk[LAY*NG*NG*HID];
__device__ float g_nodegrid[NN*NG*3];
__device__ float g_h[NN*NG*HID];
__device__ float g_agg[NN*NG*HID];
__device__ float g_readout[NN*NG*9];
__device__ float g_kbsp[(size_t)NE*NG*BAS];   // 393 MB

__device__ __forceinline__ float gelu(float x) {
    return x * 0.5f * (1.0f + erff(x * 0.70710678118654752f));
}

// ---------------- K0: fibonacci sphere ----------------
__global__ void k_init_grid0() {
    int i = threadIdx.x;
    if (i < NG) {
        const float golden = 1.6180339887498949f;
        const float twopi  = 6.2831853071795865f;
        float fi = (float)i;
        float theta = (twopi * fi) / golden;
        float z = 1.0f - (2.0f * fi + 1.0f) / (float)NG;
        float r = sqrtf(fmaxf(1.0f - z * z, 0.0f));
        g_grid0[i*3+0] = r * cosf(theta);
        g_grid0[i*3+1] = r * sinf(theta);
        g_grid0[i*3+2] = z;
    }
}

// ---------------- K1: kb_sh (144 rows) ----------------
__global__ void k_kbsh(const float* __restrict__ Wsh1, const float* __restrict__ bsh1,
                       const float* __restrict__ Wsh2, const float* __restrict__ bsh2) {
    int row = blockIdx.x;            // p*12+o
    int p = row / NG, o = row % NG;
    int c = threadIdx.x;             // 128 threads
    __shared__ float h1[HID];
    float t = g_grid0[p*3+0]*g_grid0[o*3+0] + g_grid0[p*3+1]*g_grid0[o*3+1]
            + g_grid0[p*3+2]*g_grid0[o*3+2];
    float pf0 = t, pf1 = t*t, pf2 = t*t*t;
    float a = bsh1[c] + pf0*Wsh1[0*HID+c] + pf1*Wsh1[1*HID+c] + pf2*Wsh1[2*HID+c];
    h1[c] = gelu(a);
    __syncthreads();
    float acc = bsh2[c];
    #pragma unroll 8
    for (int k = 0; k < HID; k++) acc += h1[k] * Wsh2[k*HID+c];
    g_kbsh[row*BAS + c] = gelu(acc);
}

// ---------------- K2: fk[l,p,o,:] = kb_sh[p,o,:] @ Wfk[l] ----------------
__global__ void k_fk(const float* __restrict__ Wfk) {
    int blk = blockIdx.x;            // l*144 + row
    int l = blk / (NG*NG), row = blk % (NG*NG);
    int c = threadIdx.x;
    __shared__ float kb[BAS];
    kb[c] = g_kbsh[row*BAS + c];
    __syncthreads();
    const float* W = Wfk + (size_t)l*BAS*HID;
    float acc = 0.f;
    #pragma unroll 8
    for (int b = 0; b < BAS; b++) acc += kb[b] * W[b*HID + c];
    g_fk[((size_t)l*NG*NG + row)*HID + c] = acc;
}

// ---------------- K3: node_grid + h0 + zero readout ----------------
__global__ void k_nodeinit(const float* __restrict__ x, const float* __restrict__ vec,
                           const float* __restrict__ Q, const int* __restrict__ batch,
                           const float* __restrict__ Wemb) {
    int i = blockIdx.x;
    int t = threadIdx.x;
    __shared__ float ng[NG][3];
    __shared__ float xv[NG][2];
    __shared__ float xs[IN_S];
    int b = batch[i];
    if (t < 36) {
        int n = t / 3, d = t % 3;
        float s = 0.f;
        #pragma unroll
        for (int j = 0; j < 3; j++) s += Q[b*9 + d*3 + j] * g_grid0[n*3 + j];
        ng[n][d] = s;
        g_nodegrid[i*36 + t] = s;
    }
    if (t >= 64 && t < 64 + IN_S) xs[t-64] = x[i*IN_S + (t-64)];
    if (t < 108) g_readout[i*108 + t] = 0.f;
    __syncthreads();
    if (t < 24) {
        int n = t / 2, v = t % 2;
        xv[n][v] = vec[i*6 + v*3 + 0]*ng[n][0] + vec[i*6 + v*3 + 1]*ng[n][1]
                 + vec[i*6 + v*3 + 2]*ng[n][2];
    }
    __syncthreads();
    int c = t;
    float hx = 0.f;
    #pragma unroll
    for (int s = 0; s < IN_S; s++) hx += xs[s] * Wemb[s*HID + c];
    float w16 = Wemb[16*HID + c], w17 = Wemb[17*HID + c];
    #pragma unroll
    for (int n = 0; n < NG; n++)
        g_h[(size_t)i*NG*HID + n*HID + c] = hx + xv[n][0]*w16 + xv[n][1]*w17;
}

// ---------------- K4: kb_sp per edge ----------------
__global__ void k_kbsp(const float* __restrict__ pos, const int* __restrict__ ei,
                       const float* __restrict__ Wsp1, const float* __restrict__ bsp1,
                       const float* __restrict__ Wsp2, const float* __restrict__ bsp2) {
    int e = blockIdx.x;
    int c = threadIdx.x;
    __shared__ float pf[NG][16];      // 14 used
    __shared__ float h1[NG][HID];
    int s = ei[e], r = ei[NE + e];
    float rx = pos[s*3+0] - pos[r*3+0];
    float ry = pos[s*3+1] - pos[r*3+1];
    float rz = pos[s*3+2] - pos[r*3+2];
    if (c < NG) {
        int n = c;
        float gx = g_nodegrid[r*36 + n*3 + 0];
        float gy = g_nodegrid[r*36 + n*3 + 1];
        float gz = g_nodegrid[r*36 + n*3 + 2];
        float a = rx*gx + ry*gy + rz*gz;                // inv1
        float vx = rx - a*gx, vy = ry - a*gy, vz = rz - a*gz;
        float bb = sqrtf(vx*vx + vy*vy + vz*vz);        // inv2
        pf[n][0] = a;   pf[n][1] = bb;
        pf[n][2] = a*a; pf[n][3] = a*bb; pf[n][4] = bb*a; pf[n][5] = bb*bb;
        pf[n][6]  = a*a*a;   pf[n][7]  = a*a*bb;
        pf[n][8]  = a*bb*a;  pf[n][9]  = a*bb*bb;
        pf[n][10] = bb*a*a;  pf[n][11] = bb*a*bb;
        pf[n][12] = bb*bb*a; pf[n][13] = bb*bb*bb;
    }
    __syncthreads();
    float bs1 = bsp1[c];
    #pragma unroll
    for (int n = 0; n < NG; n++) {
        float a = bs1;
        #pragma unroll
        for (int j = 0; j < 14; j++) a += pf[n][j] * Wsp1[j*HID + c];
        h1[n][c] = gelu(a);
    }
    __syncthreads();
    float acc[NG];
    #pragma unroll
    for (int n = 0; n < NG; n++) acc[n] = 0.f;
    for (int k = 0; k < HID; k += 4) {
        float w0 = Wsp2[(k+0)*HID + c];
        float w1 = Wsp2[(k+1)*HID + c];
        float w2 = Wsp2[(k+2)*HID + c];
        float w3 = Wsp2[(k+3)*HID + c];
        #pragma unroll
        for (int n = 0; n < NG; n++) {
            float4 hv = *(const float4*)&h1[n][k];
            acc[n] += hv.x*w0 + hv.y*w1 + hv.z*w2 + hv.w*w3;
        }
    }
    float bs2 = bsp2[c];
    float* out = g_kbsp + (size_t)e*NG*BAS;
    #pragma unroll
    for (int n = 0; n < NG; n++) out[n*HID + c] = gelu(acc[n] + bs2);
}

// ---------------- zero helper ----------------
__global__ void k_zero_agg() {
    size_t idx = (size_t)blockIdx.x * blockDim.x + threadIdx.x;
    size_t tot = (size_t)NN*NG*HID;
    if (idx < tot) g_agg[idx] = 0.f;
}

// ---------------- K6: edge message + scatter (per layer) ----------------
__global__ void k_edge(const float* __restrict__ Wk, const int* __restrict__ ei, int l) {
    int e = blockIdx.x;
    int c = threadIdx.x;
    __shared__ float kb[NG][HID];
    {
        const float4* src = (const float4*)(g_kbsp + (size_t)e*NG*BAS);
        float4* dst = (float4*)&kb[0][0];
        for (int i = c; i < NG*HID/4; i += HID) dst[i] = src[i];
    }
    __syncthreads();
    int s = ei[e], r = ei[NE + e];
    const float* W = Wk + (size_t)l*BAS*HID;
    float acc[NG];
    #pragma unroll
    for (int n = 0; n < NG; n++) acc[n] = 0.f;
    for (int b = 0; b < BAS; b += 4) {
        float w0 = W[(b+0)*HID + c];
        float w1 = W[(b+1)*HID + c];
        float w2 = W[(b+2)*HID + c];
        float w3 = W[(b+3)*HID + c];
        #pragma unroll
        for (int n = 0; n < NG; n++) {
            float4 kv = *(const float4*)&kb[n][b];
            acc[n] += kv.x*w0 + kv.y*w1 + kv.z*w2 + kv.w*w3;
        }
    }
    const float* hs = g_h + (size_t)s*NG*HID;
    float* ag = g_agg + (size_t)r*NG*HID;
    #pragma unroll
    for (int n = 0; n < NG; n++) {
        float m = hs[n*HID + c] * acc[n];
        atomicAdd(&ag[n*HID + c], m);
    }
}

// ---------------- K7: conv + LN + MLP + residual + readout (per layer) ----
__global__ void k_node(const float* __restrict__ bconv,
                       const float* __restrict__ lng, const float* __restrict__ lnb,
                       const float* __restrict__ W1, const float* __restrict__ b1,
                       const float* __restrict__ W2, const float* __restrict__ b2,
                       const float* __restrict__ Wro, const float* __restrict__ bro,
                       int l) {
    int i = blockIdx.x;
    int c = threadIdx.x;   // 128
    __shared__ float sA[NG][HID];    // agg
    __shared__ float sH[NG][HID];    // x2 -> hn -> h_new
    __shared__ float sU[NG][WHID];   // mlp hidden (24 KB)
    __shared__ float mu[NG], rstd[NG];
    {
        const float4* src = (const float4*)(g_agg + (size_t)i*NG*HID);
        float4* dst = (float4*)&sA[0][0];
        for (int k = c; k < NG*HID/4; k += HID) dst[k] = src[k];
    }
    __syncthreads();
    // conv: x2[p][c] = sum_o sA[o][c]*fk[l,p,o,c]/12 + bconv
    const float* fkl = g_fk + (size_t)l*NG*NG*HID;
    float bcv = bconv[l*HID + c];
    #pragma unroll
    for (int p = 0; p < NG; p++) {
        float s = 0.f;
        #pragma unroll
        for (int o = 0; o < NG; o++) s += sA[o][c] * fkl[(p*NG + o)*HID + c];
        sH[p][c] = s * (1.0f/NG) + bcv;
    }
    __syncthreads();
    // LN stats: threads 0..11
    if (c < NG) {
        float s = 0.f, s2 = 0.f;
        for (int k = 0; k < HID; k++) { float v = sH[c][k]; s += v; s2 += v*v; }
        float m = s / HID;
        float var = s2 / HID - m*m;
        mu[c] = m; rstd[c] = rsqrtf(var + 1e-5f);
    }
    __syncthreads();
    float g = lng[l*HID + c], bb = lnb[l*HID + c];
    float hn[NG];
    #pragma unroll
    for (int p = 0; p < NG; p++) hn[p] = (sH[p][c] - mu[p]) * rstd[p] * g + bb;
    __syncthreads();
    #pragma unroll
    for (int p = 0; p < NG; p++) sH[p][c] = hn[p];
    __syncthreads();
    // MLP layer 1: 128 -> 512
    const float* W1l = W1 + (size_t)l*HID*WHID;
    for (int jj = 0; jj < 4; jj++) {
        int j = c + jj*HID;
        float acc[NG];
        #pragma unroll
        for (int p = 0; p < NG; p++) acc[p] = 0.f;
        for (int k = 0; k < HID; k += 4) {
            float w0 = W1l[(k+0)*WHID + j];
            float w1 = W1l[(k+1)*WHID + j];
            float w2 = W1l[(k+2)*WHID + j];
            float w3 = W1l[(k+3)*WHID + j];
            #pragma unroll
            for (int p = 0; p < NG; p++) {
                float4 hv = *(const float4*)&sH[p][k];
                acc[p] += hv.x*w0 + hv.y*w1 + hv.z*w2 + hv.w*w3;
            }
        }
        float bj = b1[l*WHID + j];
        #pragma unroll
        for (int p = 0; p < NG; p++) sU[p][j] = gelu(acc[p] + bj);
    }
    __syncthreads();
    // MLP layer 2: 512 -> 128, residual, store h
    const float* W2l = W2 + (size_t)l*WHID*HID;
    float acc[NG];
    #pragma unroll
    for (int p = 0; p < NG; p++) acc[p] = 0.f;
    for (int j = 0; j < WHID; j += 4) {
        float w0 = W2l[(j+0)*HID + c];
        float w1 = W2l[(j+1)*HID + c];
        float w2 = W2l[(j+2)*HID + c];
        float w3 = W2l[(j+3)*HID + c];
        #pragma unroll
        for (int p = 0; p < NG; p++) {
            float4 uv = *(const float4*)&sU[p][j];
            acc[p] += uv.x*w0 + uv.y*w1 + uv.z*w2 + uv.w*w3;
        }
    }
    float b2c = b2[l*HID + c];
    float* hrow = g_h + (size_t)i*NG*HID;
    __syncthreads();
    #pragma unroll
    for (int p = 0; p < NG; p++) {
        float hnew = hrow[p*HID + c] + acc[p] + b2c;
        hrow[p*HID + c] = hnew;
        sH[p][c] = hnew;
    }
    __syncthreads();
    // readout accumulation: threads 0..107 -> (p,m)
    if (c < NG*9) {
        int p = c / 9, m = c % 9;
        const float* Wrol = Wro + (size_t)l*HID*9;
        float s = 0.f;
        for (int k = 0; k < HID; k++) s += sH[p][k] * Wrol[k*9 + m];
        g_readout[(size_t)i*108 + p*9 + m] += (s + bro[l*9 + m]) * (1.0f/LAY);
    }
}

// ---------------- K8: final reduction ----------------
__global__ void k_zero_out(float* out, int n) {
    int t = threadIdx.x;
    if (t < n) out[t] = 0.f;
}

__global__ void k_final(const int* __restrict__ batch, float* __restrict__ out) {
    int i = blockIdx.x;
    int t = threadIdx.x;
    int b = batch[i];
    if (t < OUT_S) {
        float s = 0.f;
        #pragma unroll
        for (int n = 0; n < NG; n++) s += g_readout[(size_t)i*108 + n*9 + t];
        atomicAdd(&out[b*OUT_S + t], s * (1.0f/NG));
    } else if (t < OUT_S + 3) {
        int d = t - OUT_S;
        float s = 0.f;
        #pragma unroll
        for (int n = 0; n < NG; n++)
            s += g_readout[(size_t)i*108 + n*9 + 8] * g_nodegrid[i*36 + n*3 + d];
        atomicAdd(&out[BATCH*OUT_S + b*3 + d], s * (1.0f/NG));
    }
}

// ---------------- launch ----------------
extern "C" void kernel_launch(void* const* d_in, const int* in_sizes, int n_in,
                              void* d_out, int out_size) {
    const float* x     = (const float*)d_in[0];
    const float* vec   = (const float*)d_in[1];
    const float* pos   = (const float*)d_in[2];
    const float* Q     = (const float*)d_in[3];
    const float* Wsp1  = (const float*)d_in[4];
    const float* bsp1  = (const float*)d_in[5];
    const float* Wsp2  = (const float*)d_in[6];
    const float* bsp2  = (const float*)d_in[7];
    const float* Wsh1  = (const float*)d_in[8];
    const float* bsh1  = (const float*)d_in[9];
    const float* Wsh2  = (const float*)d_in[10];
    const float* bsh2  = (const float*)d_in[11];
    const float* Wemb  = (const float*)d_in[12];
    const float* Wk    = (const float*)d_in[13];
    const float* Wfk   = (const float*)d_in[14];
    const float* bconv = (const float*)d_in[15];
    const float* lng   = (const float*)d_in[16];
    const float* lnb   = (const float*)d_in[17];
    const float* W1    = (const float*)d_in[18];
    const float* b1    = (const float*)d_in[19];
    const float* W2    = (const float*)d_in[20];
    const float* b2    = (const float*)d_in[21];
    const float* Wro   = (const float*)d_in[22];
    const float* bro   = (const float*)d_in[23];
    const int*   ei    = (const int*)d_in[24];
    const int*   batch = (const int*)d_in[25];
    float* out = (float*)d_out;

    k_init_grid0<<<1, 32>>>();
    k_kbsh<<<NG*NG, HID>>>(Wsh1, bsh1, Wsh2, bsh2);
    k_fk<<<LAY*NG*NG, HID>>>(Wfk);
    k_nodeinit<<<NN, HID>>>(x, vec, Q, batch, Wemb);
    k_kbsp<<<NE, HID>>>(pos, ei, Wsp1, bsp1, Wsp2, bsp2);

    for (int l = 0; l < LAY; l++) {
        int tot = NN*NG*HID;
        k_zero_agg<<<(tot + 255)/256, 256>>>();
        k_edge<<<NE, HID>>>(Wk, ei, l);
        k_node<<<NN, HID>>>(bconv, lng, lnb, W1, b1, W2, b2, Wro, bro, l);
    }

    k_zero_out<<<1, 1024>>>(out, out_size);
    k_final<<<NN, 32>>>(batch, out);
}

// round 4
// speedup vs baseline: 1.1394x; 1.1380x over previous
#include <cuda_runtime.h>
#include <math.h>

#define NN     8000
#define NE     64000
#define BATCH  64
#define NG     12
#define HID    128
#define BAS    128
#define LAY    3
#define IN_S   16
#define OUT_S  8
#define WIDE   4
#define WHID   (WIDE*HID)   // 512

// ---------------- device scratch (static, no allocs) ----------------
__device__ float g_grid0[NG*3];
__device__ float g_kbsh[NG*NG*BAS];
__device__ float g_fk[LAY*NG*NG*HID];
__device__ float g_nodegrid[NN*NG*3];
__device__ float g_h[NN*NG*HID];
__device__ float g_agg[NN*NG*HID];
__device__ float g_readout[NN*NG*9];
__device__ float g_kbsp[(size_t)NE*NG*BAS];   // 393 MB
// pair-interleaved weights for FFMA2: word = (W[2k][c] lo32, W[2k+1][c] hi32)
__device__ unsigned long long g_Wsp2p[64*128];
__device__ unsigned long long g_Wkp[192*128];      // 3 layers x 64 x 128
__device__ unsigned long long g_W1p[192*512];      // 3 x 64 x 512
__device__ unsigned long long g_W2p[768*128];      // 3 x 256 x 128

__device__ __forceinline__ float gelu(float x) {
    return x * 0.5f * (1.0f + erff(x * 0.70710678118654752f));
}

// packed fp32x2 FMA (FFMA2): acc.lo += a.lo*b.lo; acc.hi += a.hi*b.hi
__device__ __forceinline__ void ffma2(unsigned long long& acc,
                                      unsigned long long a, unsigned long long b) {
    asm("fma.rn.f32x2 %0, %1, %2, %0;" : "+l"(acc) : "l"(a), "l"(b));
}
__device__ __forceinline__ float f32x2_sum(unsigned long long v) {
    float lo = __uint_as_float((unsigned)(v & 0xffffffffull));
    float hi = __uint_as_float((unsigned)(v >> 32));
    return lo + hi;
}

// ---------------- K0: fibonacci sphere ----------------
__global__ void k_init_grid0() {
    int i = threadIdx.x;
    if (i < NG) {
        const float golden = 1.6180339887498949f;
        const float twopi  = 6.2831853071795865f;
        float fi = (float)i;
        float theta = (twopi * fi) / golden;
        float z = 1.0f - (2.0f * fi + 1.0f) / (float)NG;
        float r = sqrtf(fmaxf(1.0f - z * z, 0.0f));
        g_grid0[i*3+0] = r * cosf(theta);
        g_grid0[i*3+1] = r * sinf(theta);
        g_grid0[i*3+2] = z;
    }
}

// ---------------- pack weights into pair-interleaved u64 ----------------
__global__ void k_pack(const float* __restrict__ src,
                       unsigned long long* __restrict__ dst, int K2, int N) {
    int idx = blockIdx.x * blockDim.x + threadIdx.x;
    if (idx >= K2 * N) return;
    int k2 = idx / N, n = idx % N;
    float lo = src[(2*k2)    *N + n];
    float hi = src[(2*k2 + 1)*N + n];
    dst[idx] = ((unsigned long long)__float_as_uint(hi) << 32) | __float_as_uint(lo);
}

// ---------------- K1: kb_sh (144 rows) ----------------
__global__ void k_kbsh(const float* __restrict__ Wsh1, const float* __restrict__ bsh1,
                       const float* __restrict__ Wsh2, const float* __restrict__ bsh2) {
    int row = blockIdx.x;
    int p = row / NG, o = row % NG;
    int c = threadIdx.x;
    __shared__ float h1[HID];
    float t = g_grid0[p*3+0]*g_grid0[o*3+0] + g_grid0[p*3+1]*g_grid0[o*3+1]
            + g_grid0[p*3+2]*g_grid0[o*3+2];
    float a = bsh1[c] + t*Wsh1[0*HID+c] + t*t*Wsh1[1*HID+c] + t*t*t*Wsh1[2*HID+c];
    h1[c] = gelu(a);
    __syncthreads();
    float acc = bsh2[c];
    #pragma unroll 8
    for (int k = 0; k < HID; k++) acc += h1[k] * Wsh2[k*HID+c];
    g_kbsh[row*BAS + c] = gelu(acc);
}

// ---------------- K2: fk ----------------
__global__ void k_fk(const float* __restrict__ Wfk) {
    int blk = blockIdx.x;
    int l = blk / (NG*NG), row = blk % (NG*NG);
    int c = threadIdx.x;
    __shared__ float kb[BAS];
    kb[c] = g_kbsh[row*BAS + c];
    __syncthreads();
    const float* W = Wfk + (size_t)l*BAS*HID;
    float acc = 0.f;
    #pragma unroll 8
    for (int b = 0; b < BAS; b++) acc += kb[b] * W[b*HID + c];
    g_fk[((size_t)l*NG*NG + row)*HID + c] = acc;
}

// ---------------- K3: node_grid + h0 + zero readout ----------------
__global__ void k_nodeinit(const float* __restrict__ x, const float* __restrict__ vec,
                           const float* __restrict__ Q, const int* __restrict__ batch,
                           const float* __restrict__ Wemb) {
    int i = blockIdx.x;
    int t = threadIdx.x;
    __shared__ float ng[NG][3];
    __shared__ float xv[NG][2];
    __shared__ float xs[IN_S];
    int b = batch[i];
    if (t < 36) {
        int n = t / 3, d = t % 3;
        float s = 0.f;
        #pragma unroll
        for (int j = 0; j < 3; j++) s += Q[b*9 + d*3 + j] * g_grid0[n*3 + j];
        ng[n][d] = s;
        g_nodegrid[i*36 + t] = s;
    }
    if (t >= 64 && t < 64 + IN_S) xs[t-64] = x[i*IN_S + (t-64)];
    if (t < 108) g_readout[i*108 + t] = 0.f;
    __syncthreads();
    if (t < 24) {
        int n = t / 2, v = t % 2;
        xv[n][v] = vec[i*6 + v*3 + 0]*ng[n][0] + vec[i*6 + v*3 + 1]*ng[n][1]
                 + vec[i*6 + v*3 + 2]*ng[n][2];
    }
    __syncthreads();
    int c = t;
    float hx = 0.f;
    #pragma unroll
    for (int s = 0; s < IN_S; s++) hx += xs[s] * Wemb[s*HID + c];
    float w16 = Wemb[16*HID + c], w17 = Wemb[17*HID + c];
    #pragma unroll
    for (int n = 0; n < NG; n++)
        g_h[(size_t)i*NG*HID + n*HID + c] = hx + xv[n][0]*w16 + xv[n][1]*w17;
}

// ---------------- K4: kb_sp per edge (MLP2 via FFMA2) ----------------
__global__ void k_kbsp(const float* __restrict__ pos, const int* __restrict__ ei,
                       const float* __restrict__ Wsp1, const float* __restrict__ bsp1,
                       const float* __restrict__ bsp2) {
    int e = blockIdx.x;
    int c = threadIdx.x;
    __shared__ float pf[NG][16];
    __shared__ __align__(16) float h1[NG][HID];
    int s = ei[e], r = ei[NE + e];
    float rx = pos[s*3+0] - pos[r*3+0];
    float ry = pos[s*3+1] - pos[r*3+1];
    float rz = pos[s*3+2] - pos[r*3+2];
    if (c < NG) {
        int n = c;
        float gx = g_nodegrid[r*36 + n*3 + 0];
        float gy = g_nodegrid[r*36 + n*3 + 1];
        float gz = g_nodegrid[r*36 + n*3 + 2];
        float a = rx*gx + ry*gy + rz*gz;
        float vx = rx - a*gx, vy = ry - a*gy, vz = rz - a*gz;
        float bb = sqrtf(vx*vx + vy*vy + vz*vz);
        pf[n][0] = a;   pf[n][1] = bb;
        pf[n][2] = a*a; pf[n][3] = a*bb; pf[n][4] = bb*a; pf[n][5] = bb*bb;
        pf[n][6]  = a*a*a;   pf[n][7]  = a*a*bb;
        pf[n][8]  = a*bb*a;  pf[n][9]  = a*bb*bb;
        pf[n][10] = bb*a*a;  pf[n][11] = bb*a*bb;
        pf[n][12] = bb*bb*a; pf[n][13] = bb*bb*bb;
    }
    __syncthreads();
    float bs1 = bsp1[c];
    #pragma unroll
    for (int n = 0; n < NG; n++) {
        float a = bs1;
        #pragma unroll
        for (int j = 0; j < 14; j++) a += pf[n][j] * Wsp1[j*HID + c];
        h1[n][c] = gelu(a);
    }
    __syncthreads();
    unsigned long long acc2[NG];
    #pragma unroll
    for (int n = 0; n < NG; n++) acc2[n] = 0ull;
    for (int k = 0; k < HID; k += 4) {
        unsigned long long w0 = g_Wsp2p[(k>>1)*HID + c];
        unsigned long long w1 = g_Wsp2p[((k>>1)+1)*HID + c];
        #pragma unroll
        for (int n = 0; n < NG; n++) {
            ulonglong2 hv = *(const ulonglong2*)&h1[n][k];
            ffma2(acc2[n], hv.x, w0);
            ffma2(acc2[n], hv.y, w1);
        }
    }
    float bs2 = bsp2[c];
    float* out = g_kbsp + (size_t)e*NG*BAS;
    #pragma unroll
    for (int n = 0; n < NG; n++) out[n*HID + c] = gelu(f32x2_sum(acc2[n]) + bs2);
}

// ---------------- zero helper ----------------
__global__ void k_zero_agg() {
    size_t idx = (size_t)blockIdx.x * blockDim.x + threadIdx.x;
    size_t tot = (size_t)NN*NG*HID;
    if (idx < tot) g_agg[idx] = 0.f;
}

// ---------------- K6: edge message + scatter (FFMA2 GEMM) ----------------
__global__ void k_edge(const int* __restrict__ ei, int l) {
    int e = blockIdx.x;
    int c = threadIdx.x;
    __shared__ __align__(16) float kb[NG][HID];
    {
        const float4* src = (const float4*)(g_kbsp + (size_t)e*NG*BAS);
        float4* dst = (float4*)&kb[0][0];
        for (int i = c; i < NG*HID/4; i += HID) dst[i] = src[i];
    }
    __syncthreads();
    int s = ei[e], r = ei[NE + e];
    const unsigned long long* Wp = g_Wkp + (size_t)l*64*HID;
    unsigned long long acc2[NG];
    #pragma unroll
    for (int n = 0; n < NG; n++) acc2[n] = 0ull;
    for (int b = 0; b < BAS; b += 4) {
        unsigned long long w0 = Wp[(b>>1)*HID + c];
        unsigned long long w1 = Wp[((b>>1)+1)*HID + c];
        #pragma unroll
        for (int n = 0; n < NG; n++) {
            ulonglong2 kv = *(const ulonglong2*)&kb[n][b];
            ffma2(acc2[n], kv.x, w0);
            ffma2(acc2[n], kv.y, w1);
        }
    }
    const float* hs = g_h + (size_t)s*NG*HID;
    float* ag = g_agg + (size_t)r*NG*HID;
    #pragma unroll
    for (int n = 0; n < NG; n++) {
        float m = hs[n*HID + c] * f32x2_sum(acc2[n]);
        atomicAdd(&ag[n*HID + c], m);
    }
}

// ---------------- K7: conv + LN + MLP + residual + readout ----------------
__global__ void k_node(const float* __restrict__ bconv,
                       const float* __restrict__ lng, const float* __restrict__ lnb,
                       const float* __restrict__ b1, const float* __restrict__ b2,
                       const float* __restrict__ Wro, const float* __restrict__ bro,
                       int l) {
    int i = blockIdx.x;
    int c = threadIdx.x;   // 128
    __shared__ __align__(16) float sA[NG][HID];
    __shared__ __align__(16) float sH[NG][HID];
    __shared__ __align__(16) float sU[NG][WHID];
    __shared__ float mu[NG], rstd[NG];
    {
        const float4* src = (const float4*)(g_agg + (size_t)i*NG*HID);
        float4* dst = (float4*)&sA[0][0];
        for (int k = c; k < NG*HID/4; k += HID) dst[k] = src[k];
    }
    __syncthreads();
    const float* fkl = g_fk + (size_t)l*NG*NG*HID;
    float bcv = bconv[l*HID + c];
    #pragma unroll
    for (int p = 0; p < NG; p++) {
        float s = 0.f;
        #pragma unroll
        for (int o = 0; o < NG; o++) s += sA[o][c] * fkl[(p*NG + o)*HID + c];
        sH[p][c] = s * (1.0f/NG) + bcv;
    }
    __syncthreads();
    if (c < NG) {
        float s = 0.f, s2 = 0.f;
        for (int k = 0; k < HID; k++) { float v = sH[c][k]; s += v; s2 += v*v; }
        float m = s / HID;
        float var = s2 / HID - m*m;
        mu[c] = m; rstd[c] = rsqrtf(var + 1e-5f);
    }
    __syncthreads();
    float g = lng[l*HID + c], bb = lnb[l*HID + c];
    float hn[NG];
    #pragma unroll
    for (int p = 0; p < NG; p++) hn[p] = (sH[p][c] - mu[p]) * rstd[p] * g + bb;
    __syncthreads();
    #pragma unroll
    for (int p = 0; p < NG; p++) sH[p][c] = hn[p];
    __syncthreads();
    // MLP layer 1: 128 -> 512 (FFMA2)
    const unsigned long long* W1p = g_W1p + (size_t)l*64*WHID;
    for (int jj = 0; jj < 4; jj++) {
        int j = c + jj*HID;
        unsigned long long acc2[NG];
        #pragma unroll
        for (int p = 0; p < NG; p++) acc2[p] = 0ull;
        for (int k = 0; k < HID; k += 4) {
            unsigned long long w0 = W1p[(k>>1)*WHID + j];
            unsigned long long w1 = W1p[((k>>1)+1)*WHID + j];
            #pragma unroll
            for (int p = 0; p < NG; p++) {
                ulonglong2 hv = *(const ulonglong2*)&sH[p][k];
                ffma2(acc2[p], hv.x, w0);
                ffma2(acc2[p], hv.y, w1);
            }
        }
        float bj = b1[l*WHID + j];
        #pragma unroll
        for (int p = 0; p < NG; p++) sU[p][j] = gelu(f32x2_sum(acc2[p]) + bj);
    }
    __syncthreads();
    // MLP layer 2: 512 -> 128 (FFMA2), residual, store h
    const unsigned long long* W2p = g_W2p + (size_t)l*256*HID;
    unsigned long long acc2[NG];
    #pragma unroll
    for (int p = 0; p < NG; p++) acc2[p] = 0ull;
    for (int k = 0; k < WHID; k += 4) {
        unsigned long long w0 = W2p[(k>>1)*HID + c];
        unsigned long long w1 = W2p[((k>>1)+1)*HID + c];
        #pragma unroll
        for (int p = 0; p < NG; p++) {
            ulonglong2 uv = *(const ulonglong2*)&sU[p][k];
            ffma2(acc2[p], uv.x, w0);
            ffma2(acc2[p], uv.y, w1);
        }
    }
    float b2c = b2[l*HID + c];
    float* hrow = g_h + (size_t)i*NG*HID;
    __syncthreads();
    #pragma unroll
    for (int p = 0; p < NG; p++) {
        float hnew = hrow[p*HID + c] + f32x2_sum(acc2[p]) + b2c;
        hrow[p*HID + c] = hnew;
        sH[p][c] = hnew;
    }
    __syncthreads();
    if (c < NG*9) {
        int p = c / 9, m = c % 9;
        const float* Wrol = Wro + (size_t)l*HID*9;
        float s = 0.f;
        for (int k = 0; k < HID; k++) s += sH[p][k] * Wrol[k*9 + m];
        g_readout[(size_t)i*108 + p*9 + m] += (s + bro[l*9 + m]) * (1.0f/LAY);
    }
}

// ---------------- K8: final reduction ----------------
__global__ void k_zero_out(float* out, int n) {
    int t = threadIdx.x;
    if (t < n) out[t] = 0.f;
}

__global__ void k_final(const int* __restrict__ batch, float* __restrict__ out) {
    int i = blockIdx.x;
    int t = threadIdx.x;
    int b = batch[i];
    if (t < OUT_S) {
        float s = 0.f;
        #pragma unroll
        for (int n = 0; n < NG; n++) s += g_readout[(size_t)i*108 + n*9 + t];
        atomicAdd(&out[b*OUT_S + t], s * (1.0f/NG));
    } else if (t < OUT_S + 3) {
        int d = t - OUT_S;
        float s = 0.f;
        #pragma unroll
        for (int n = 0; n < NG; n++)
            s += g_readout[(size_t)i*108 + n*9 + 8] * g_nodegrid[i*36 + n*3 + d];
        atomicAdd(&out[BATCH*OUT_S + b*3 + d], s * (1.0f/NG));
    }
}

// ---------------- launch ----------------
extern "C" void kernel_launch(void* const* d_in, const int* in_sizes, int n_in,
                              void* d_out, int out_size) {
    const float* x     = (const float*)d_in[0];
    const float* vec   = (const float*)d_in[1];
    const float* pos   = (const float*)d_in[2];
    const float* Q     = (const float*)d_in[3];
    const float* Wsp1  = (const float*)d_in[4];
    const float* bsp1  = (const float*)d_in[5];
    const float* Wsp2  = (const float*)d_in[6];
    const float* bsp2  = (const float*)d_in[7];
    const float* Wsh1  = (const float*)d_in[8];
    const float* bsh1  = (const float*)d_in[9];
    const float* Wsh2  = (const float*)d_in[10];
    const float* bsh2  = (const float*)d_in[11];
    const float* Wemb  = (const float*)d_in[12];
    const float* Wk    = (const float*)d_in[13];
    const float* Wfk   = (const float*)d_in[14];
    const float* bconv = (const float*)d_in[15];
    const float* lng   = (const float*)d_in[16];
    const float* lnb   = (const float*)d_in[17];
    const float* W1    = (const float*)d_in[18];
    const float* b1    = (const float*)d_in[19];
    const float* W2    = (const float*)d_in[20];
    const float* b2    = (const float*)d_in[21];
    const float* Wro   = (const float*)d_in[22];
    const float* bro   = (const float*)d_in[23];
    const int*   ei    = (const int*)d_in[24];
    const int*   batch = (const int*)d_in[25];
    float* out = (float*)d_out;

    unsigned long long *dWsp2p, *dWkp, *dW1p, *dW2p;
    cudaGetSymbolAddress((void**)&dWsp2p, g_Wsp2p);
    cudaGetSymbolAddress((void**)&dWkp,  g_Wkp);
    cudaGetSymbolAddress((void**)&dW1p,  g_W1p);
    cudaGetSymbolAddress((void**)&dW2p,  g_W2p);

    k_init_grid0<<<1, 32>>>();
    k_pack<<<(64*128 + 255)/256, 256>>>(Wsp2, dWsp2p, 64, 128);
    k_pack<<<(192*128 + 255)/256, 256>>>(Wk, dWkp, 192, 128);
    k_pack<<<(192*512 + 255)/256, 256>>>(W1, dW1p, 192, 512);
    k_pack<<<(768*128 + 255)/256, 256>>>(W2, dW2p, 768, 128);
    k_kbsh<<<NG*NG, HID>>>(Wsh1, bsh1, Wsh2, bsh2);
    k_fk<<<LAY*NG*NG, HID>>>(Wfk);
    k_nodeinit<<<NN, HID>>>(x, vec, Q, batch, Wemb);
    k_kbsp<<<NE, HID>>>(pos, ei, Wsp1, bsp1, bsp2);

    for (int l = 0; l < LAY; l++) {
        int tot = NN*NG*HID;
        k_zero_agg<<<(tot + 255)/256, 256>>>();
        k_edge<<<NE, HID>>>(ei, l);
        k_node<<<NN, HID>>>(bconv, lng, lnb, b1, b2, Wro, bro, l);
    }

    k_zero_out<<<1, 1024>>>(out, out_size);
    k_final<<<NN, 32>>>(batch, out);
}